// round 16
// baseline (speedup 1.0000x reference)
#include <cuda_runtime.h>
#include <cuda_fp16.h>

#define N_NODES_MAX 100000
#define E_MAX 1600000
#define IN_CH 128
#define HID 64
#define N_CLASSES 16
#define N_GRAPHS 64

// Scratch (device globals; no allocation allowed).
__device__ __align__(256) float  g_dis[N_NODES_MAX];                 // deg -> rsqrt(deg)
__device__ __align__(256) __half g_bufA[(size_t)N_NODES_MAX * HID];  // 12.8 MB (gemm out, fp16)
__device__ __align__(256) __half g_bufB[(size_t)N_NODES_MAX * HID];  // 12.8 MB (layer out, fp16)
__device__ __align__(256) float  g_pool[N_GRAPHS * HID];
__device__ __align__(256) float  g_cnt[N_GRAPHS];
// CSR by destination
__device__ __align__(256) int    g_cnt_i[N_NODES_MAX];
__device__ __align__(256) int    g_rowtmp[N_NODES_MAX];
__device__ __align__(256) int    g_rowptr[N_NODES_MAX + 1];
__device__ __align__(256) int    g_fill[N_NODES_MAX];
__device__ __align__(256) int    g_bsums[128];
__device__ __align__(256) int2   g_edge[E_MAX];                      // {src, bits(ew*dis[src])}

// ---------------- init: deg=1 (self loop), counts=0, pool zero ----------------
__global__ void k_init(int N) {
    int i = blockIdx.x * blockDim.x + threadIdx.x;
    if (i < N) { g_dis[i] = 1.0f; g_cnt_i[i] = 0; }
    if (i < N_GRAPHS * HID) g_pool[i] = 0.f;
    if (i < N_GRAPHS) g_cnt[i] = 0.f;
}

// ---------------- per-edge: count + weighted degree ----------------
__global__ void k_count_deg(const int* __restrict__ ei,
                            const float* __restrict__ ew, int E) {
    int e = blockIdx.x * blockDim.x + threadIdx.x;
    if (e < E) {
        int d = ei[E + e];
        atomicAdd(&g_cnt_i[d], 1);
        atomicAdd(&g_dis[d], ew[e]);
    }
}

// ---------------- prefix scan ----------------
__global__ __launch_bounds__(1024) void k_scan1(int N) {
    __shared__ int sh[1024];
    int i = blockIdx.x * 1024 + threadIdx.x;
    int v = (i < N) ? g_cnt_i[i] : 0;
    sh[threadIdx.x] = v;
    __syncthreads();
    for (int off = 1; off < 1024; off <<= 1) {
        int t = (threadIdx.x >= off) ? sh[threadIdx.x - off] : 0;
        __syncthreads();
        sh[threadIdx.x] += t;
        __syncthreads();
    }
    if (i < N) g_rowtmp[i] = sh[threadIdx.x] - v;  // exclusive
    if (threadIdx.x == 1023) g_bsums[blockIdx.x] = sh[1023];
}

// rowptr = rowtmp + block-sum prefix (re-derived per block in smem);
// also fill cursor init and dis=rsqrt(deg).
__global__ void k_scan3(int N, int E, int nb) {
    __shared__ int sh[128];
    int t = threadIdx.x;
    if (t < nb) sh[t] = g_bsums[t];
    __syncthreads();
    if (t == 0) {
        int run = 0;
        for (int j = 0; j < nb; j++) { int c = sh[j]; sh[j] = run; run += c; }
    }
    __syncthreads();
    int i = blockIdx.x * blockDim.x + t;
    if (i < N) {
        int rp = g_rowtmp[i] + sh[i >> 10];
        g_rowptr[i] = rp;
        g_fill[i] = rp;
        g_dis[i] = rsqrtf(g_dis[i]);
    }
    if (i == 0) g_rowptr[N] = E;
}

// ---------------- fill CSR: edge -> slot, weight folded with dis[src] ----------------
__global__ void k_fill(const int* __restrict__ ei,
                       const float* __restrict__ ew, int E) {
    int e = blockIdx.x * blockDim.x + threadIdx.x;
    if (e < E) {
        int s = ei[e];
        int d = ei[E + e];
        float w = ew[e] * g_dis[s];
        int slot = atomicAdd(&g_fill[d], 1);
        g_edge[slot] = make_int2(s, __float_as_int(w));
    }
}

// ---------------- tensor-core GEMM: bufA = half( X @ W )  (no dis — folded elsewhere) ----
// 128-row tile per block, 256 threads = 8 warps, each warp 16 rows x 64 cols.
// mma.sync.m16n8k16 fp16 x fp16 -> fp32. X/W converted to fp16 in smem.
// src==0: X = Xf (fp32, input features). src==1: X = g_bufB (fp16, prev layer).
template <int K>
__global__ __launch_bounds__(256) void k_gemm_tc(const float* __restrict__ Xf,
                                                 const float* __restrict__ W,
                                                 int N, int src) {
    const int SX = 72;  // smem stride (halves); 72*2B=144B -> conflict-free quad access
    __shared__ __half Xh[128 * SX];
    __shared__ __half Wh[64 * SX];

    int t = threadIdx.x;
    int rowbase = blockIdx.x * 128;
    int lane = t & 31;
    int gID = lane >> 2;   // 0..7
    int t4 = lane & 3;     // 0..3
    int m_local = (t >> 5) * 16;

    float acc[8][4] = {};

    for (int kc = 0; kc < K; kc += 64) {
        // load X chunk: 128 rows x 64 halves (2048 x uint2)
        for (int f = t; f < 2048; f += 256) {
            int r = f >> 4;            // 16 uint2 per row
            int q = (f & 15) << 2;     // half offset 0..60
            int row = rowbase + r;
            uint2 hv = make_uint2(0u, 0u);
            if (row < N) {
                if (src == 0) {
                    float4 v = *(const float4*)(Xf + (size_t)row * K + kc + q);
                    __half2 p0 = __floats2half2_rn(v.x, v.y);
                    __half2 p1 = __floats2half2_rn(v.z, v.w);
                    hv.x = *(unsigned*)&p0;
                    hv.y = *(unsigned*)&p1;
                } else {
                    hv = *(const uint2*)(g_bufB + (size_t)row * K + kc + q);
                }
            }
            *(uint2*)&Xh[r * SX + q] = hv;
        }
        // load W chunk transposed: Wh[n][k] (column-major K x 64)
        for (int f = t; f < 4096; f += 256) {
            int kl = f >> 6;
            int c = f & 63;
            Wh[c * SX + kl] = __float2half(W[(size_t)(kc + kl) * 64 + c]);
        }
        __syncthreads();

#pragma unroll
        for (int kk = 0; kk < 64; kk += 16) {
            unsigned a0 = *(unsigned*)&Xh[(m_local + gID) * SX + kk + t4 * 2];
            unsigned a1 = *(unsigned*)&Xh[(m_local + gID + 8) * SX + kk + t4 * 2];
            unsigned a2 = *(unsigned*)&Xh[(m_local + gID) * SX + kk + 8 + t4 * 2];
            unsigned a3 = *(unsigned*)&Xh[(m_local + gID + 8) * SX + kk + 8 + t4 * 2];
#pragma unroll
            for (int j = 0; j < 8; j++) {
                int n = j * 8 + gID;
                unsigned b0 = *(unsigned*)&Wh[n * SX + kk + t4 * 2];
                unsigned b1 = *(unsigned*)&Wh[n * SX + kk + 8 + t4 * 2];
                asm volatile(
                    "mma.sync.aligned.m16n8k16.row.col.f32.f16.f16.f32 "
                    "{%0,%1,%2,%3}, {%4,%5,%6,%7}, {%8,%9}, {%0,%1,%2,%3};"
                    : "+f"(acc[j][0]), "+f"(acc[j][1]), "+f"(acc[j][2]), "+f"(acc[j][3])
                    : "r"(a0), "r"(a1), "r"(a2), "r"(a3), "r"(b0), "r"(b1));
            }
        }
        __syncthreads();
    }

    // epilogue: store fp16 (no dis scaling)
    int r0 = rowbase + m_local + gID;
    int r1 = r0 + 8;
    if (r0 < N) {
#pragma unroll
        for (int j = 0; j < 8; j++) {
            __half2 h = __floats2half2_rn(acc[j][0], acc[j][1]);
            *(__half2*)&g_bufA[(size_t)r0 * HID + j * 8 + t4 * 2] = h;
        }
    }
    if (r1 < N) {
#pragma unroll
        for (int j = 0; j < 8; j++) {
            __half2 h = __floats2half2_rn(acc[j][2], acc[j][3]);
            *(__half2*)&g_bufA[(size_t)r1 * HID + j * 8 + t4 * 2] = h;
        }
    }
}

// ---------------- gather + dis + bias + relu (4 nodes/warp, 8 lanes each) ----------------
// Each 8-lane group owns one node; lane holds uint4 = 8 halves (full 128B row per group).
// Four independent 2-wide-pipelined chains per warp -> 4x concurrent latency chains.
// acc = dis[node]*h[node] + sum w'*h[src];  out = dis[node]*acc + b, relu.
__global__ __launch_bounds__(256) void k_gather(const float* __restrict__ bias, int N) {
    int gid = blockIdx.x * 256 + threadIdx.x;
    int node = gid >> 3;
    if (node >= N) return;
    int lane = threadIdx.x & 7;    // 0..7 within group

    const uint4* G = (const uint4*)g_bufA;   // 8 uint4 per node row
    int base = node * 8 + lane;
    float ds = g_dis[node];

    uint4 sv = G[base];
    float2 s0 = __half22float2(*(__half2*)&sv.x);
    float2 s1 = __half22float2(*(__half2*)&sv.y);
    float2 s2 = __half22float2(*(__half2*)&sv.z);
    float2 s3 = __half22float2(*(__half2*)&sv.w);
    float acc0 = ds * s0.x, acc1 = ds * s0.y, acc2 = ds * s1.x, acc3 = ds * s1.y;
    float acc4 = ds * s2.x, acc5 = ds * s2.y, acc6 = ds * s3.x, acc7 = ds * s3.y;

    int k = __ldg(&g_rowptr[node]);
    int s1e = __ldg(&g_rowptr[node + 1]);

    int2 e0, e1;
    bool have2 = (k + 1 < s1e);
    if (have2) { e0 = g_edge[k]; e1 = g_edge[k + 1]; }
    while (have2) {
        int2 c0 = e0, c1 = e1;
        k += 2;
        have2 = (k + 1 < s1e);
        if (have2) { e0 = g_edge[k]; e1 = g_edge[k + 1]; }  // prefetch next pair
        uint4 u0 = G[c0.x * 8 + lane];
        uint4 u1 = G[c1.x * 8 + lane];
        float w0 = __int_as_float(c0.y);
        float w1 = __int_as_float(c1.y);
        float2 a0 = __half22float2(*(__half2*)&u0.x);
        float2 a1 = __half22float2(*(__half2*)&u0.y);
        float2 a2 = __half22float2(*(__half2*)&u0.z);
        float2 a3 = __half22float2(*(__half2*)&u0.w);
        acc0 = fmaf(w0, a0.x, acc0); acc1 = fmaf(w0, a0.y, acc1);
        acc2 = fmaf(w0, a1.x, acc2); acc3 = fmaf(w0, a1.y, acc3);
        acc4 = fmaf(w0, a2.x, acc4); acc5 = fmaf(w0, a2.y, acc5);
        acc6 = fmaf(w0, a3.x, acc6); acc7 = fmaf(w0, a3.y, acc7);
        float2 b0 = __half22float2(*(__half2*)&u1.x);
        float2 b1 = __half22float2(*(__half2*)&u1.y);
        float2 b2 = __half22float2(*(__half2*)&u1.z);
        float2 b3 = __half22float2(*(__half2*)&u1.w);
        acc0 = fmaf(w1, b0.x, acc0); acc1 = fmaf(w1, b0.y, acc1);
        acc2 = fmaf(w1, b1.x, acc2); acc3 = fmaf(w1, b1.y, acc3);
        acc4 = fmaf(w1, b2.x, acc4); acc5 = fmaf(w1, b2.y, acc5);
        acc6 = fmaf(w1, b3.x, acc6); acc7 = fmaf(w1, b3.y, acc7);
    }
    if (k < s1e) {
        int2 c0 = g_edge[k];
        uint4 u0 = G[c0.x * 8 + lane];
        float w0 = __int_as_float(c0.y);
        float2 a0 = __half22float2(*(__half2*)&u0.x);
        float2 a1 = __half22float2(*(__half2*)&u0.y);
        float2 a2 = __half22float2(*(__half2*)&u0.z);
        float2 a3 = __half22float2(*(__half2*)&u0.w);
        acc0 = fmaf(w0, a0.x, acc0); acc1 = fmaf(w0, a0.y, acc1);
        acc2 = fmaf(w0, a1.x, acc2); acc3 = fmaf(w0, a1.y, acc3);
        acc4 = fmaf(w0, a2.x, acc4); acc5 = fmaf(w0, a2.y, acc5);
        acc6 = fmaf(w0, a3.x, acc6); acc7 = fmaf(w0, a3.y, acc7);
    }

    float4 bv0 = *(const float4*)(bias + lane * 8);
    float4 bv1 = *(const float4*)(bias + lane * 8 + 4);
    float o0 = fmaf(ds, acc0, bv0.x);
    float o1 = fmaf(ds, acc1, bv0.y);
    float o2 = fmaf(ds, acc2, bv0.z);
    float o3 = fmaf(ds, acc3, bv0.w);
    float o4 = fmaf(ds, acc4, bv1.x);
    float o5 = fmaf(ds, acc5, bv1.y);
    float o6 = fmaf(ds, acc6, bv1.z);
    float o7 = fmaf(ds, acc7, bv1.w);
    o0 = o0 > 0.f ? o0 : 0.f;  o1 = o1 > 0.f ? o1 : 0.f;
    o2 = o2 > 0.f ? o2 : 0.f;  o3 = o3 > 0.f ? o3 : 0.f;
    o4 = o4 > 0.f ? o4 : 0.f;  o5 = o5 > 0.f ? o5 : 0.f;
    o6 = o6 > 0.f ? o6 : 0.f;  o7 = o7 > 0.f ? o7 : 0.f;
    __half2 h0 = __floats2half2_rn(o0, o1);
    __half2 h1 = __floats2half2_rn(o2, o3);
    __half2 h2 = __floats2half2_rn(o4, o5);
    __half2 h3 = __floats2half2_rn(o6, o7);
    uint4 ov;
    ov.x = *(unsigned*)&h0;
    ov.y = *(unsigned*)&h1;
    ov.z = *(unsigned*)&h2;
    ov.w = *(unsigned*)&h3;
    ((uint4*)g_bufB)[base] = ov;
}

// ---------------- pooling (256-row chunks) ----------------
#define POOL_CHUNK 256
__global__ __launch_bounds__(256) void k_pool(const int* __restrict__ batch, int N) {
    int base = blockIdx.x * POOL_CHUNK;
    int c = threadIdx.x & 63;
    int r0 = threadIdx.x >> 6;  // 0..3
    int end = base + POOL_CHUNK;
    if (end > N) end = N;

    float s = 0.f, n = 0.f;
    int cur = -1;
    for (int i = base + r0; i < end; i += 4) {
        int gi = batch[i];
        if (gi != cur) {
            if (cur >= 0) {
                atomicAdd(g_pool + cur * 64 + c, s);
                if (c == 0) atomicAdd(g_cnt + cur, n);
            }
            cur = gi; s = 0.f; n = 0.f;
        }
        s += __half2float(g_bufB[(size_t)i * HID + c]);
        n += 1.f;
    }
    if (cur >= 0) {
        atomicAdd(g_pool + cur * 64 + c, s);
        if (c == 0) atomicAdd(g_cnt + cur, n);
    }
}

// ---------------- head ----------------
__global__ void k_head(const float* __restrict__ Wl, const float* __restrict__ bl,
                       float* __restrict__ out) {
    int t = threadIdx.x;
    if (t >= N_GRAPHS * N_CLASSES) return;
    int g = t >> 4;
    int j = t & 15;
    float inv = 1.f / fmaxf(g_cnt[g], 1.f);
    float a = bl[j];
#pragma unroll
    for (int c = 0; c < 64; c++)
        a = fmaf(g_pool[g * 64 + c] * inv, Wl[c * 16 + j], a);
    out[t] = a;
}

// ---------------- launch ----------------
extern "C" void kernel_launch(void* const* d_in, const int* in_sizes, int n_in,
                              void* d_out, int out_size) {
    const float* x = (const float*)d_in[0];
    const int* ei = (const int*)d_in[1];      // int32 (JAX x64 disabled)
    const float* ew = (const float*)d_in[2];
    const int* batch = (const int*)d_in[3];   // int32
    const float* W1 = (const float*)d_in[4];
    const float* b1 = (const float*)d_in[5];
    const float* W2 = (const float*)d_in[6];
    const float* b2 = (const float*)d_in[7];
    const float* Wl = (const float*)d_in[8];
    const float* bl = (const float*)d_in[9];
    float* out = (float*)d_out;

    int N = in_sizes[0] / IN_CH;   // 100000
    int E = in_sizes[2];           // 1600000

    // one-time side stream + events (host-side objects only; no device alloc)
    static cudaStream_t s_side = nullptr;
    static cudaEvent_t s_evF = nullptr, s_evJ = nullptr;
    if (!s_side) {
        cudaStreamCreateWithFlags(&s_side, cudaStreamNonBlocking);
        cudaEventCreateWithFlags(&s_evF, cudaEventDisableTiming);
        cudaEventCreateWithFlags(&s_evJ, cudaEventDisableTiming);
    }

    int tb = 256;
    int nblk = (N + tb - 1) / tb;
    int eblk = (E + tb - 1) / tb;
    int nb_scan = (N + 1023) / 1024;
    int gemm_blocks = (N + 127) / 128;
    int gather_blocks = (N * 8 + tb - 1) / tb;

    // ---- fork: GEMM1 (independent of CSR/dis) on side stream ----
    cudaEventRecord(s_evF, 0);
    cudaStreamWaitEvent(s_side, s_evF, 0);
    k_gemm_tc<IN_CH><<<gemm_blocks, tb, 0, s_side>>>(x, W1, N, 0);  // A = half(x@W1)
    cudaEventRecord(s_evJ, s_side);

    // ---- CSR build + degree on main stream (concurrent with GEMM1) ----
    k_init<<<nblk, tb>>>(N);
    k_count_deg<<<eblk, tb>>>(ei, ew, E);
    k_scan1<<<nb_scan, 1024>>>(N);
    k_scan3<<<nblk, tb>>>(N, E, nb_scan);
    k_fill<<<eblk, tb>>>(ei, ew, E);

    // ---- join: gather1 needs both CSR and GEMM1 ----
    cudaStreamWaitEvent(0, s_evJ, 0);

    // layer 1 aggregation
    k_gather<<<gather_blocks, tb>>>(b1, N);               // B = relu(dis*(dis*A + agg w'*A) + b1)

    // layer 2
    k_gemm_tc<HID><<<gemm_blocks, tb>>>(x, W2, N, 1);     // A = half(B@W2)
    k_gather<<<gather_blocks, tb>>>(b2, N);               // B = relu(... + b2)

    // pooling + head
    k_pool<<<(N + POOL_CHUNK - 1) / POOL_CHUNK, tb>>>(batch, N);
    k_head<<<1, 1024>>>(Wl, bl, out);
}

// round 17
// speedup vs baseline: 1.0695x; 1.0695x over previous
#include <cuda_runtime.h>
#include <cuda_fp16.h>

#define N_NODES_MAX 100000
#define E_MAX 1600000
#define IN_CH 128
#define HID 64
#define N_CLASSES 16
#define N_GRAPHS 64

// Scratch (device globals; no allocation allowed).
// Self-cleaning protocol: every launch leaves g_deg / g_cnt_i / g_pool / g_cnt /
// g_bsums zeroed (first launch relies on static zero-init), so no init kernel
// is needed on the critical path.
__device__ __align__(256) float  g_dis[N_NODES_MAX];                 // rsqrt(1+deg)
__device__ __align__(256) float  g_deg[N_NODES_MAX];                 // weighted degree acc
__device__ __align__(256) __half g_bufA[(size_t)N_NODES_MAX * HID];  // 12.8 MB (gemm out)
__device__ __align__(256) __half g_bufB[(size_t)N_NODES_MAX * HID];  // 12.8 MB (layer out)
__device__ __align__(256) float  g_pool[N_GRAPHS * HID];
__device__ __align__(256) float  g_cnt[N_GRAPHS];
// CSR by destination
__device__ __align__(256) int    g_cnt_i[N_NODES_MAX];
__device__ __align__(256) int    g_rowptr[N_NODES_MAX + 1];
__device__ __align__(256) int    g_fill[N_NODES_MAX];
__device__ __align__(256) int    g_bsums[128];                       // total+1, 0 = not ready
__device__ __align__(256) int2   g_edge[E_MAX];                      // {src, bits(ew*dis[src])}

// ---------------- per-edge: count + weighted degree ----------------
__global__ void k_count_deg(const int* __restrict__ ei,
                            const float* __restrict__ ew, int E) {
    int e = blockIdx.x * blockDim.x + threadIdx.x;
    if (e < E) {
        int d = ei[E + e];
        atomicAdd(&g_cnt_i[d], 1);
        atomicAdd(&g_deg[d], ew[e]);
    }
}

// ---------------- merged scan: rowptr + fill cursor + dis, self-cleaning ----------------
// Hillis-Steele within block; block totals published via atomicExch (total+1),
// decoupled lookback sums predecessors (all publish independently -> no serial chain).
__global__ __launch_bounds__(1024) void k_scan(int N, int E) {
    __shared__ int sh[1024];
    __shared__ int s_prefix;
    int b = blockIdx.x;
    int t = threadIdx.x;
    int i = b * 1024 + t;

    int v = 0;
    if (i < N) { v = g_cnt_i[i]; g_cnt_i[i] = 0; }   // read + self-clean
    sh[t] = v;
    __syncthreads();
    for (int off = 1; off < 1024; off <<= 1) {
        int u = (t >= off) ? sh[t - off] : 0;
        __syncthreads();
        sh[t] += u;
        __syncthreads();
    }

    if (t == 0) {
        __threadfence();
        atomicExch(&g_bsums[b], sh[1023] + 1);       // publish block total (+1 = ready)
        int pre = 0;
        for (int j = 0; j < b; j++) {
            int val;
            do { val = atomicAdd(&g_bsums[j], 0); } while (val == 0);
            pre += val - 1;
        }
        s_prefix = pre;
    }
    __syncthreads();
    int prefix = s_prefix;

    if (i < N) {
        int rp = prefix + sh[t] - v;                  // exclusive scan
        g_rowptr[i] = rp;
        g_fill[i] = rp;
        float dg = g_deg[i];
        g_deg[i] = 0.f;                               // self-clean
        g_dis[i] = rsqrtf(1.0f + dg);                 // +1 = self-loop weight
    }
    if (i == 0) g_rowptr[N] = E;
}

// ---------------- fill CSR: edge -> slot, weight folded with dis[src] ----------------
__global__ void k_fill(const int* __restrict__ ei,
                       const float* __restrict__ ew, int E) {
    int e = blockIdx.x * blockDim.x + threadIdx.x;
    if (e < E) {
        int s = ei[e];
        int d = ei[E + e];
        float w = ew[e] * g_dis[s];
        int slot = atomicAdd(&g_fill[d], 1);
        g_edge[slot] = make_int2(s, __float_as_int(w));
    }
}

// ---------------- tensor-core GEMM: bufA = half( X @ W )  (no dis — folded elsewhere) ----
template <int K>
__global__ __launch_bounds__(256) void k_gemm_tc(const float* __restrict__ Xf,
                                                 const float* __restrict__ W,
                                                 int N, int src) {
    const int SX = 72;  // smem stride (halves); conflict-free quad access
    __shared__ __half Xh[128 * SX];
    __shared__ __half Wh[64 * SX];

    int t = threadIdx.x;
    int rowbase = blockIdx.x * 128;
    int lane = t & 31;
    int gID = lane >> 2;   // 0..7
    int t4 = lane & 3;     // 0..3
    int m_local = (t >> 5) * 16;

    float acc[8][4] = {};

    for (int kc = 0; kc < K; kc += 64) {
        for (int f = t; f < 2048; f += 256) {
            int r = f >> 4;
            int q = (f & 15) << 2;
            int row = rowbase + r;
            uint2 hv = make_uint2(0u, 0u);
            if (row < N) {
                if (src == 0) {
                    float4 v = *(const float4*)(Xf + (size_t)row * K + kc + q);
                    __half2 p0 = __floats2half2_rn(v.x, v.y);
                    __half2 p1 = __floats2half2_rn(v.z, v.w);
                    hv.x = *(unsigned*)&p0;
                    hv.y = *(unsigned*)&p1;
                } else {
                    hv = *(const uint2*)(g_bufB + (size_t)row * K + kc + q);
                }
            }
            *(uint2*)&Xh[r * SX + q] = hv;
        }
        for (int f = t; f < 4096; f += 256) {
            int kl = f >> 6;
            int c = f & 63;
            Wh[c * SX + kl] = __float2half(W[(size_t)(kc + kl) * 64 + c]);
        }
        __syncthreads();

#pragma unroll
        for (int kk = 0; kk < 64; kk += 16) {
            unsigned a0 = *(unsigned*)&Xh[(m_local + gID) * SX + kk + t4 * 2];
            unsigned a1 = *(unsigned*)&Xh[(m_local + gID + 8) * SX + kk + t4 * 2];
            unsigned a2 = *(unsigned*)&Xh[(m_local + gID) * SX + kk + 8 + t4 * 2];
            unsigned a3 = *(unsigned*)&Xh[(m_local + gID + 8) * SX + kk + 8 + t4 * 2];
#pragma unroll
            for (int j = 0; j < 8; j++) {
                int n = j * 8 + gID;
                unsigned b0 = *(unsigned*)&Wh[n * SX + kk + t4 * 2];
                unsigned b1 = *(unsigned*)&Wh[n * SX + kk + 8 + t4 * 2];
                asm volatile(
                    "mma.sync.aligned.m16n8k16.row.col.f32.f16.f16.f32 "
                    "{%0,%1,%2,%3}, {%4,%5,%6,%7}, {%8,%9}, {%0,%1,%2,%3};"
                    : "+f"(acc[j][0]), "+f"(acc[j][1]), "+f"(acc[j][2]), "+f"(acc[j][3])
                    : "r"(a0), "r"(a1), "r"(a2), "r"(a3), "r"(b0), "r"(b1));
            }
        }
        __syncthreads();
    }

    int r0 = rowbase + m_local + gID;
    int r1 = r0 + 8;
    if (r0 < N) {
#pragma unroll
        for (int j = 0; j < 8; j++) {
            __half2 h = __floats2half2_rn(acc[j][0], acc[j][1]);
            *(__half2*)&g_bufA[(size_t)r0 * HID + j * 8 + t4 * 2] = h;
        }
    }
    if (r1 < N) {
#pragma unroll
        for (int j = 0; j < 8; j++) {
            __half2 h = __floats2half2_rn(acc[j][2], acc[j][3]);
            *(__half2*)&g_bufA[(size_t)r1 * HID + j * 8 + t4 * 2] = h;
        }
    }
}

// ---------------- gather + dis + bias + relu (2 nodes/warp, 16 lanes each) ----------------
// Round-15 optimum: two independent 2-wide-pipelined chains per warp.
// acc = dis[node]*h[node] + sum w'*h[src];  out = dis[node]*acc + b, relu.
__global__ __launch_bounds__(256) void k_gather(const float* __restrict__ bias, int N) {
    int gid = blockIdx.x * 256 + threadIdx.x;
    int node = gid >> 4;
    if (node >= N) return;
    int lane = threadIdx.x & 15;   // 0..15 within group

    const uint2* G = (const uint2*)g_bufA;   // 16 uint2 per node row
    int base = node * 16 + lane;
    float ds = g_dis[node];

    uint2 sv = G[base];
    float2 p0 = __half22float2(*(__half2*)&sv.x);
    float2 p1 = __half22float2(*(__half2*)&sv.y);
    float4 acc = make_float4(ds * p0.x, ds * p0.y, ds * p1.x, ds * p1.y);

    int k = __ldg(&g_rowptr[node]);
    int s1 = __ldg(&g_rowptr[node + 1]);

    int2 e0, e1;
    bool have2 = (k + 1 < s1);
    if (have2) { e0 = g_edge[k]; e1 = g_edge[k + 1]; }
    while (have2) {
        int2 c0 = e0, c1 = e1;
        k += 2;
        have2 = (k + 1 < s1);
        if (have2) { e0 = g_edge[k]; e1 = g_edge[k + 1]; }  // prefetch next pair
        uint2 u0 = G[c0.x * 16 + lane];
        uint2 u1 = G[c1.x * 16 + lane];
        float w0 = __int_as_float(c0.y);
        float w1 = __int_as_float(c1.y);
        float2 a0 = __half22float2(*(__half2*)&u0.x);
        float2 b0 = __half22float2(*(__half2*)&u0.y);
        float2 a1 = __half22float2(*(__half2*)&u1.x);
        float2 b1 = __half22float2(*(__half2*)&u1.y);
        acc.x = fmaf(w0, a0.x, acc.x); acc.y = fmaf(w0, a0.y, acc.y);
        acc.z = fmaf(w0, b0.x, acc.z); acc.w = fmaf(w0, b0.y, acc.w);
        acc.x = fmaf(w1, a1.x, acc.x); acc.y = fmaf(w1, a1.y, acc.y);
        acc.z = fmaf(w1, b1.x, acc.z); acc.w = fmaf(w1, b1.y, acc.w);
    }
    if (k < s1) {
        int2 c0 = g_edge[k];
        uint2 u0 = G[c0.x * 16 + lane];
        float w0 = __int_as_float(c0.y);
        float2 a0 = __half22float2(*(__half2*)&u0.x);
        float2 b0 = __half22float2(*(__half2*)&u0.y);
        acc.x = fmaf(w0, a0.x, acc.x); acc.y = fmaf(w0, a0.y, acc.y);
        acc.z = fmaf(w0, b0.x, acc.z); acc.w = fmaf(w0, b0.y, acc.w);
    }

    float4 bv = *(const float4*)(bias + lane * 4);
    float o0 = fmaf(ds, acc.x, bv.x);
    float o1 = fmaf(ds, acc.y, bv.y);
    float o2 = fmaf(ds, acc.z, bv.z);
    float o3 = fmaf(ds, acc.w, bv.w);
    o0 = o0 > 0.f ? o0 : 0.f;
    o1 = o1 > 0.f ? o1 : 0.f;
    o2 = o2 > 0.f ? o2 : 0.f;
    o3 = o3 > 0.f ? o3 : 0.f;
    __half2 h0 = __floats2half2_rn(o0, o1);
    __half2 h1 = __floats2half2_rn(o2, o3);
    uint2 ov;
    ov.x = *(unsigned*)&h0;
    ov.y = *(unsigned*)&h1;
    ((uint2*)g_bufB)[base] = ov;
}

// ---------------- pooling (256-row chunks) ----------------
#define POOL_CHUNK 256
__global__ __launch_bounds__(256) void k_pool(const int* __restrict__ batch, int N) {
    int base = blockIdx.x * POOL_CHUNK;
    int c = threadIdx.x & 63;
    int r0 = threadIdx.x >> 6;  // 0..3
    int end = base + POOL_CHUNK;
    if (end > N) end = N;

    float s = 0.f, n = 0.f;
    int cur = -1;
    for (int i = base + r0; i < end; i += 4) {
        int gi = batch[i];
        if (gi != cur) {
            if (cur >= 0) {
                atomicAdd(g_pool + cur * 64 + c, s);
                if (c == 0) atomicAdd(g_cnt + cur, n);
            }
            cur = gi; s = 0.f; n = 0.f;
        }
        s += __half2float(g_bufB[(size_t)i * HID + c]);
        n += 1.f;
    }
    if (cur >= 0) {
        atomicAdd(g_pool + cur * 64 + c, s);
        if (c == 0) atomicAdd(g_cnt + cur, n);
    }
}

// ---------------- head: compute out, then self-clean pool/cnt/bsums ----------------
__global__ void k_head(const float* __restrict__ Wl, const float* __restrict__ bl,
                       float* __restrict__ out) {
    int t = threadIdx.x;
    if (t < N_GRAPHS * N_CLASSES) {
        int g = t >> 4;
        int j = t & 15;
        float inv = 1.f / fmaxf(g_cnt[g], 1.f);
        float a = bl[j];
#pragma unroll
        for (int c = 0; c < 64; c++)
            a = fmaf(g_pool[g * 64 + c] * inv, Wl[c * 16 + j], a);
        out[t] = a;
    }
    __syncthreads();
    // self-clean for next launch
    for (int i = t; i < N_GRAPHS * HID; i += 1024) g_pool[i] = 0.f;
    if (t < N_GRAPHS) g_cnt[t] = 0.f;
    if (t < 128) g_bsums[t] = 0;
}

// ---------------- launch ----------------
extern "C" void kernel_launch(void* const* d_in, const int* in_sizes, int n_in,
                              void* d_out, int out_size) {
    const float* x = (const float*)d_in[0];
    const int* ei = (const int*)d_in[1];      // int32 (JAX x64 disabled)
    const float* ew = (const float*)d_in[2];
    const int* batch = (const int*)d_in[3];   // int32
    const float* W1 = (const float*)d_in[4];
    const float* b1 = (const float*)d_in[5];
    const float* W2 = (const float*)d_in[6];
    const float* b2 = (const float*)d_in[7];
    const float* Wl = (const float*)d_in[8];
    const float* bl = (const float*)d_in[9];
    float* out = (float*)d_out;

    int N = in_sizes[0] / IN_CH;   // 100000
    int E = in_sizes[2];           // 1600000

    // one-time side stream + events (host-side objects only; no device alloc)
    static cudaStream_t s_side = nullptr;
    static cudaEvent_t s_evF = nullptr, s_evJ = nullptr;
    if (!s_side) {
        cudaStreamCreateWithFlags(&s_side, cudaStreamNonBlocking);
        cudaEventCreateWithFlags(&s_evF, cudaEventDisableTiming);
        cudaEventCreateWithFlags(&s_evJ, cudaEventDisableTiming);
    }

    int tb = 256;
    int eblk = (E + tb - 1) / tb;
    int nb_scan = (N + 1023) / 1024;
    int gemm_blocks = (N + 127) / 128;
    int gather_blocks = (N * 16 + tb - 1) / tb;

    // ---- fork: GEMM1 (independent of CSR/dis) on side stream ----
    cudaEventRecord(s_evF, 0);
    cudaStreamWaitEvent(s_side, s_evF, 0);
    k_gemm_tc<IN_CH><<<gemm_blocks, tb, 0, s_side>>>(x, W1, N, 0);  // A = half(x@W1)
    cudaEventRecord(s_evJ, s_side);

    // ---- CSR build on main stream (3 launches; counters pre-zeroed by protocol) ----
    k_count_deg<<<eblk, tb>>>(ei, ew, E);
    k_scan<<<nb_scan, 1024>>>(N, E);
    k_fill<<<eblk, tb>>>(ei, ew, E);

    // ---- join: gather1 needs both CSR and GEMM1 ----
    cudaStreamWaitEvent(0, s_evJ, 0);

    // layer 1 aggregation
    k_gather<<<gather_blocks, tb>>>(b1, N);               // B = relu(dis*(dis*A + agg w'*A) + b1)

    // layer 2
    k_gemm_tc<HID><<<gemm_blocks, tb>>>(x, W2, N, 1);     // A = half(B@W2)
    k_gather<<<gather_blocks, tb>>>(b2, N);               // B = relu(... + b2)

    // pooling + head (head self-cleans pool/cnt/bsums)
    k_pool<<<(N + POOL_CHUNK - 1) / POOL_CHUNK, tb>>>(batch, N);
    k_head<<<1, 1024>>>(Wl, bl, out);
}